// round 1
// baseline (speedup 1.0000x reference)
#include <cuda_runtime.h>
#include <stdint.h>

// Problem constants (fixed by the reference)
#define BATCH 128
#define NN    512
#define NBINS 100
#define WPR   (NN / 32)   // 16 words per bitset row

// Scratch (allocation-free: __device__ globals)
__device__ uint32_t g_bits[2][BATCH][NN][WPR];   // 8.4 MB packed adjacency
__device__ int      g_hist[2][BATCH][NBINS];     // histogram counts
__device__ float    g_acc[3];                    // Kxx, Kyy, Kxy sums

// ---------------------------------------------------------------------------
// Kernel 0: zero histograms + accumulators (deterministic every call)
// ---------------------------------------------------------------------------
__global__ void zero_kernel() {
    int t = blockIdx.x * blockDim.x + threadIdx.x;
    const int nh = 2 * BATCH * NBINS;
    if (t < nh) reinterpret_cast<int*>(g_hist)[t] = 0;
    if (t < 3)  g_acc[t] = 0.0f;
}

// ---------------------------------------------------------------------------
// Kernel 1: pack float adjacency into bitsets via warp ballot.
// One thread per element; lane l of each warp owns bit l of one 32-bit word.
// ---------------------------------------------------------------------------
__global__ void pack_kernel(const float* __restrict__ a1,
                            const float* __restrict__ a2) {
    long long t = (long long)blockIdx.x * blockDim.x + threadIdx.x;
    const long long per = (long long)BATCH * NN * NN;   // multiple of 32 -> no warp straddle
    float v = (t < per) ? a1[t] : a2[t - per];
    unsigned m = __ballot_sync(0xffffffffu, v != 0.0f);
    if ((threadIdx.x & 31) == 0)
        reinterpret_cast<uint32_t*>(g_bits)[t >> 5] = m;
}

// ---------------------------------------------------------------------------
// Kernel 2: per-node clustering coefficient + histogram.
// One warp per (set, batch, node). tri2_i = sum_{j in N(i)} popc(row_i & row_j).
// ---------------------------------------------------------------------------
__global__ void cluster_kernel() {
    int gw   = (blockIdx.x * blockDim.x + threadIdx.x) >> 5;  // global warp id
    int lane = threadIdx.x & 31;
    int s = gw >> 16;          // / (128*512)
    int r = gw & 0xFFFF;
    int b = r >> 9;            // / 512
    int i = r & 511;

    __shared__ uint32_t sh[8][WPR];  // 8 warps per block
    int wl = threadIdx.x >> 5;

    uint32_t wi = (lane < WPR) ? g_bits[s][b][i][lane] : 0u;
    if (lane < WPR) sh[wl][lane] = wi;
    __syncwarp();

    int deg = __reduce_add_sync(0xffffffffu, __popc(wi));

    const uint32_t* rw = sh[wl];
    int tri = 0;
#pragma unroll
    for (int t = 0; t < WPR; ++t) {
        // lane handles candidate neighbor j = t*32 + lane; bit is rw[t] >> lane
        if ((rw[t] >> lane) & 1u) {
            int j = t * 32 + lane;
            const uint4* rj = reinterpret_cast<const uint4*>(g_bits[s][b][j]);
            int c = 0;
#pragma unroll
            for (int q = 0; q < 4; ++q) {
                uint4 v4 = rj[q];
                c += __popc(rw[4*q + 0] & v4.x) + __popc(rw[4*q + 1] & v4.y)
                   + __popc(rw[4*q + 2] & v4.z) + __popc(rw[4*q + 3] & v4.w);
            }
            tri += c;
        }
    }
    tri = __reduce_add_sync(0xffffffffu, tri);

    if (lane == 0) {
        int bin = 0;
        if (deg >= 2) {
            // IEEE-exact to match JAX fp32: c = tri/denom, idx = trunc(c*100), clip
            float denom = (float)deg * (float)(deg - 1);
            float c  = __fdiv_rn((float)tri, denom);
            float cb = __fmul_rn(c, (float)NBINS);
            bin = (int)cb;
            bin = bin < 0 ? 0 : (bin > NBINS - 1 ? NBINS - 1 : bin);
        }
        atomicAdd(&g_hist[s][b][bin], 1);
    }
}

// ---------------------------------------------------------------------------
// Kernel 3: RBF kernel-matrix sums. grid=(128, 3): y-dim selects Kxx/Kyy/Kxy.
// Block (i, m): thread j computes exp(-||h_x[i]-h_y[j]||^2 / 2).
// ---------------------------------------------------------------------------
__global__ void mmd_kernel() {
    int i = blockIdx.x;
    int m = blockIdx.y;          // 0: (h1,h1)  1: (h2,h2)  2: (h1,h2)
    int j = threadIdx.x;         // 128 threads

    const int* hx = g_hist[(m == 1) ? 1 : 0][i];
    const int* hy = g_hist[(m == 0) ? 0 : 1][j];

    __shared__ float xs[NBINS];
    if (j < NBINS) xs[j] = (float)hx[j];
    __syncthreads();

    float d2 = 0.0f;
#pragma unroll 4
    for (int k = 0; k < NBINS; ++k) {
        float d = xs[k] - (float)hy[k];
        d2 = fmaf(d, d, d2);
    }
    float kv = expf(-0.5f * d2);

    // warp reduce, then one atomic per warp
#pragma unroll
    for (int o = 16; o; o >>= 1)
        kv += __shfl_down_sync(0xffffffffu, kv, o);
    if ((threadIdx.x & 31) == 0)
        atomicAdd(&g_acc[m], kv);
}

// ---------------------------------------------------------------------------
// Kernel 4: finalize scalar MMD
// ---------------------------------------------------------------------------
__global__ void final_kernel(float* __restrict__ out) {
    const float inv = 1.0f / (128.0f * 128.0f);
    out[0] = (g_acc[0] + g_acc[1] - 2.0f * g_acc[2]) * inv;
}

// ---------------------------------------------------------------------------
extern "C" void kernel_launch(void* const* d_in, const int* in_sizes, int n_in,
                              void* d_out, int out_size) {
    const float* a1 = (const float*)d_in[0];
    const float* a2 = (const float*)d_in[1];

    zero_kernel<<<128, 256>>>();

    long long total = 2LL * BATCH * NN * NN;            // 67,108,864 elements
    pack_kernel<<<(unsigned)(total / 256), 256>>>(a1, a2);

    // 2*128*512 = 131072 warps, 8 warps (256 thr) per block
    cluster_kernel<<<(2 * BATCH * NN) / 8, 256>>>();

    dim3 g(BATCH, 3);
    mmd_kernel<<<g, 128>>>();

    final_kernel<<<1, 1>>>((float*)d_out);
}

// round 2
// speedup vs baseline: 1.3882x; 1.3882x over previous
#include <cuda_runtime.h>
#include <stdint.h>

// Problem constants (fixed by the reference)
#define BATCH 128
#define NN    512
#define NBINS 100
#define WPR   (NN / 32)   // 16 words per bitset row

// Scratch (allocation-free: __device__ globals)
__device__ uint32_t g_bits[2][BATCH][NN][WPR];   // 8.4 MB packed adjacency
__device__ int      g_hist[2][BATCH][NBINS];     // histogram counts
__device__ float    g_acc[3];                    // Kxx, Kyy, Kxy sums

// ---------------------------------------------------------------------------
// Kernel 0: zero the 3 accumulators (hist is fully overwritten by cluster_kernel)
// ---------------------------------------------------------------------------
__global__ void zero_kernel() {
    if (threadIdx.x < 3) g_acc[threadIdx.x] = 0.0f;
}

// ---------------------------------------------------------------------------
// Kernel 1: pack float adjacency into bitsets via warp ballot.
// One thread per element; lane l of each warp owns bit l of one 32-bit word.
// DRAM-bound (268 MB read) -- this is the unavoidable floor.
// ---------------------------------------------------------------------------
__global__ void pack_kernel(const float* __restrict__ a1,
                            const float* __restrict__ a2) {
    long long t = (long long)blockIdx.x * blockDim.x + threadIdx.x;
    const long long per = (long long)BATCH * NN * NN;   // multiple of 32 -> no warp straddle
    float v = (t < per) ? a1[t] : a2[t - per];
    unsigned m = __ballot_sync(0xffffffffu, v != 0.0f);
    if ((threadIdx.x & 31) == 0)
        reinterpret_cast<uint32_t*>(g_bits)[t >> 5] = m;
}

// ---------------------------------------------------------------------------
// Kernel 2: clustering coefficient + histogram, one BLOCK per graph.
// Whole 32KB bitset staged in smem (rows padded to 17 words: stride 17 is odd,
// so cross-row word-k accesses are bank-conflict-free). One thread per node:
// enumerate neighbors from register-resident own row, 16 LDS+AND+POPC each.
// Block-local smem histogram -> direct (non-atomic) global store.
// ---------------------------------------------------------------------------
__global__ void __launch_bounds__(512) cluster_kernel() {
    int sb = blockIdx.x;          // 0..255
    int s  = sb >> 7;
    int b  = sb & (BATCH - 1);

    __shared__ uint32_t rows[NN][WPR + 1];   // 512*17*4 = 34816 B
    __shared__ int shist[NBINS];

    // stage bitset (coalesced 8192-word copy)
    const uint32_t* __restrict__ src = &g_bits[s][b][0][0];
    for (int t = threadIdx.x; t < NN * WPR; t += 512)
        rows[t >> 4][t & 15] = src[t];
    if (threadIdx.x < NBINS) shist[threadIdx.x] = 0;
    __syncthreads();

    int i = threadIdx.x;   // this thread's node
    uint32_t my[WPR];
    int deg = 0;
#pragma unroll
    for (int w = 0; w < WPR; ++w) { my[w] = rows[i][w]; deg += __popc(my[w]); }

    int tri = 0;
#pragma unroll
    for (int w = 0; w < WPR; ++w) {
        uint32_t m = my[w];
        while (m) {
            int j = (w << 5) + (__ffs(m) - 1);
            m &= m - 1;
            const uint32_t* rj = rows[j];
            int c = 0;
#pragma unroll
            for (int w2 = 0; w2 < WPR; ++w2) c += __popc(my[w2] & rj[w2]);
            tri += c;
        }
    }

    int bin = 0;
    if (deg >= 2) {
        // IEEE-exact to match JAX fp32: c = tri/denom, idx = trunc(c*100), clip
        float denom = (float)deg * (float)(deg - 1);
        float c  = __fdiv_rn((float)tri, denom);
        float cb = __fmul_rn(c, (float)NBINS);
        bin = (int)cb;
        bin = bin < 0 ? 0 : (bin > NBINS - 1 ? NBINS - 1 : bin);
    }
    atomicAdd(&shist[bin], 1);
    __syncthreads();

    if (threadIdx.x < NBINS)
        g_hist[s][b][threadIdx.x] = shist[threadIdx.x];   // block owns this slot
}

// ---------------------------------------------------------------------------
// Kernel 3: RBF kernel-matrix sums. grid=(128, 3): y-dim selects Kxx/Kyy/Kxy.
// Stage all 128 hy rows in smem (stride 101 -> conflict-free) + xs row.
// ---------------------------------------------------------------------------
__global__ void mmd_kernel() {
    int i = blockIdx.x;
    int m = blockIdx.y;          // 0: (h1,h1)  1: (h2,h2)  2: (h1,h2)
    int j = threadIdx.x;         // 128 threads

    const int* __restrict__ hx  = g_hist[(m == 1) ? 1 : 0][i];
    const int* __restrict__ hy0 = g_hist[(m == 0) ? 0 : 1][0];

    __shared__ float xs[NBINS];
    __shared__ float ys[BATCH][NBINS + 1];   // 51.7 KB, stride 101

    for (int t = j; t < BATCH * NBINS; t += 128)
        ys[t / NBINS][t % NBINS] = (float)hy0[t];
    if (j < NBINS) xs[j] = (float)hx[j];
    __syncthreads();

    float d2 = 0.0f;
#pragma unroll 4
    for (int k = 0; k < NBINS; ++k) {
        float d = xs[k] - ys[j][k];
        d2 = fmaf(d, d, d2);
    }
    float kv = expf(-0.5f * d2);

#pragma unroll
    for (int o = 16; o; o >>= 1)
        kv += __shfl_down_sync(0xffffffffu, kv, o);
    if ((j & 31) == 0)
        atomicAdd(&g_acc[m], kv);
}

// ---------------------------------------------------------------------------
// Kernel 4: finalize scalar MMD
// ---------------------------------------------------------------------------
__global__ void final_kernel(float* __restrict__ out) {
    const float inv = 1.0f / (128.0f * 128.0f);
    out[0] = (g_acc[0] + g_acc[1] - 2.0f * g_acc[2]) * inv;
}

// ---------------------------------------------------------------------------
extern "C" void kernel_launch(void* const* d_in, const int* in_sizes, int n_in,
                              void* d_out, int out_size) {
    const float* a1 = (const float*)d_in[0];
    const float* a2 = (const float*)d_in[1];

    zero_kernel<<<1, 32>>>();

    long long total = 2LL * BATCH * NN * NN;            // 67,108,864 elements
    pack_kernel<<<(unsigned)(total / 256), 256>>>(a1, a2);

    cluster_kernel<<<2 * BATCH, 512>>>();               // one block per graph

    dim3 g(BATCH, 3);
    mmd_kernel<<<g, 128>>>();

    final_kernel<<<1, 1>>>((float*)d_out);
}

// round 3
// speedup vs baseline: 2.8945x; 2.0850x over previous
#include <cuda_runtime.h>
#include <stdint.h>

// Problem constants (fixed by the reference)
#define BATCH 128
#define NN    512
#define NBINS 100
#define WPR   (NN / 32)   // 16 words per bitset row

// Scratch (allocation-free: __device__ globals)
__device__ float g_histf[2][BATCH][NBINS];   // histograms (exact small ints)
__device__ float g_acc[3];                   // Kxx, Kyy, Kxy sums

// ---------------------------------------------------------------------------
// Kernel 0: zero the 3 accumulators
// ---------------------------------------------------------------------------
__global__ void zero_kernel() {
    if (threadIdx.x < 3) g_acc[threadIdx.x] = 0.0f;
}

// ---------------------------------------------------------------------------
// Kernel 1 (FUSED pack + cluster): one block per graph.
//  Phase A: stream 1MB of fp32 adjacency with contiguous float4 loads,
//           pack to a 512x512 bitset in smem via a 3-step shfl tree.
//  Phase B: per-node triangle count from smem (rows padded to 17 words ->
//           odd stride -> conflict-free divergent row reads).
//  Phase C: block-local histogram -> direct global store (block owns slot).
// ---------------------------------------------------------------------------
__global__ void __launch_bounds__(512) cluster_kernel(
        const float* __restrict__ a1, const float* __restrict__ a2) {
    int sb = blockIdx.x;          // 0..255
    int s  = sb >> 7;
    int b  = sb & (BATCH - 1);

    __shared__ uint32_t rows[NN][WPR + 1];   // 512*17*4 = 34816 B
    __shared__ int shist[NBINS];

    int wid  = threadIdx.x >> 5;
    int lane = threadIdx.x & 31;

    // ---- Phase A: pack directly from global floats ----
    const float4* __restrict__ src =
        reinterpret_cast<const float4*>((s ? a2 : a1) + (size_t)b * NN * NN);

    for (int r = wid; r < NN; r += 16) {           // 32 rows per warp
        const float4* p = src + r * (NN / 4);      // 128 float4 per row
#pragma unroll
        for (int q = 0; q < 4; ++q) {
            // contiguous per-warp load: lanes cover 128 consecutive floats
            float4 v = p[q * 32 + lane];
            uint32_t nib = (uint32_t)(v.x != 0.0f)
                         | ((uint32_t)(v.y != 0.0f) << 1)
                         | ((uint32_t)(v.z != 0.0f) << 2)
                         | ((uint32_t)(v.w != 0.0f) << 3);
            // shfl tree: gather 8 lanes' nibbles into one ordered 32-bit word
            uint32_t t;
            t = __shfl_xor_sync(0xffffffffu, nib, 1);
            nib = (lane & 1) ? (t | (nib << 4))  : (nib | (t << 4));
            t = __shfl_xor_sync(0xffffffffu, nib, 2);
            nib = (lane & 2) ? (t | (nib << 8))  : (nib | (t << 8));
            t = __shfl_xor_sync(0xffffffffu, nib, 4);
            nib = (lane & 4) ? (t | (nib << 16)) : (nib | (t << 16));
            if ((lane & 7) == 0)
                rows[r][4 * q + (lane >> 3)] = nib;   // word = cols [32w,32w+32)
        }
    }
    if (threadIdx.x < NBINS) shist[threadIdx.x] = 0;
    __syncthreads();

    // ---- Phase B: triangles. One thread per node. ----
    int i = threadIdx.x;
    uint32_t my[WPR];
    int deg = 0;
#pragma unroll
    for (int w = 0; w < WPR; ++w) { my[w] = rows[i][w]; deg += __popc(my[w]); }

    int tri = 0;
#pragma unroll
    for (int w = 0; w < WPR; ++w) {
        uint32_t m = my[w];
        while (m) {
            int j = (w << 5) + (__ffs(m) - 1);
            m &= m - 1;
            const uint32_t* rj = rows[j];
            int c = 0;
#pragma unroll
            for (int w2 = 0; w2 < WPR; ++w2) c += __popc(my[w2] & rj[w2]);
            tri += c;
        }
    }

    // ---- Phase C: bin (IEEE-exact vs JAX fp32) + histogram ----
    int bin = 0;
    if (deg >= 2) {
        float denom = (float)deg * (float)(deg - 1);
        float c  = __fdiv_rn((float)tri, denom);
        float cb = __fmul_rn(c, (float)NBINS);
        bin = (int)cb;
        bin = bin < 0 ? 0 : (bin > NBINS - 1 ? NBINS - 1 : bin);
    }
    atomicAdd(&shist[bin], 1);
    __syncthreads();

    if (threadIdx.x < NBINS)
        g_histf[s][b][threadIdx.x] = (float)shist[threadIdx.x];
}

// ---------------------------------------------------------------------------
// Kernel 2: RBF kernel-matrix sums. grid=(8,3): 16 i-rows per block, so the
// 51KB ys staging is amortized 16x. Stride 101 (odd) -> conflict-free.
// ---------------------------------------------------------------------------
__global__ void mmd_kernel() {
    int m = blockIdx.y;          // 0: (h1,h1)  1: (h2,h2)  2: (h1,h2)
    int j = threadIdx.x;         // 128 threads

    const float* __restrict__ hx0 = &g_histf[(m == 1) ? 1 : 0][0][0];
    const float* __restrict__ hy0 = &g_histf[(m == 0) ? 0 : 1][0][0];

    __shared__ float xs[NBINS];
    __shared__ float ys[BATCH][NBINS + 1];   // stride 101

    for (int t = j; t < BATCH * NBINS; t += 128)
        ys[t / NBINS][t % NBINS] = hy0[t];
    __syncthreads();

    float acc = 0.0f;
    for (int ii = 0; ii < 16; ++ii) {
        int i = blockIdx.x * 16 + ii;
        if (j < NBINS) xs[j] = hx0[i * NBINS + j];
        __syncthreads();

        float d2 = 0.0f;
#pragma unroll 4
        for (int k = 0; k < NBINS; ++k) {
            float d = xs[k] - ys[j][k];
            d2 = fmaf(d, d, d2);
        }
        acc += expf(-0.5f * d2);
        __syncthreads();
    }

#pragma unroll
    for (int o = 16; o; o >>= 1)
        acc += __shfl_down_sync(0xffffffffu, acc, o);
    if ((j & 31) == 0)
        atomicAdd(&g_acc[m], acc);
}

// ---------------------------------------------------------------------------
// Kernel 3: finalize scalar MMD
// ---------------------------------------------------------------------------
__global__ void final_kernel(float* __restrict__ out) {
    const float inv = 1.0f / (128.0f * 128.0f);
    out[0] = (g_acc[0] + g_acc[1] - 2.0f * g_acc[2]) * inv;
}

// ---------------------------------------------------------------------------
extern "C" void kernel_launch(void* const* d_in, const int* in_sizes, int n_in,
                              void* d_out, int out_size) {
    const float* a1 = (const float*)d_in[0];
    const float* a2 = (const float*)d_in[1];

    zero_kernel<<<1, 32>>>();
    cluster_kernel<<<2 * BATCH, 512>>>(a1, a2);   // fused pack + triangles
    dim3 g(8, 3);
    mmd_kernel<<<g, 128>>>();
    final_kernel<<<1, 1>>>((float*)d_out);
}